// round 5
// baseline (speedup 1.0000x reference)
#include <cuda_runtime.h>

// Problem constants: B=256, T=2048, I=2, H=128, 3H=384
#define BB 256
#define TT 2048
#define HH 128
#define NTHREADS 384

__device__ int d_order[BB];

// Plain descending-length order (R2-proven): wave 1 = 148 longest, wave-2
// CTAs work-stolen in bid order = LPT.
__global__ void order_kernel(const int* __restrict__ lengths) {
    int i = threadIdx.x;
    int li = lengths[i];
    int rank = 0;
    #pragma unroll 8
    for (int j = 0; j < BB; j++) {
        int lj = lengths[j];
        rank += (lj > li) || (lj == li && j < i);
    }
    d_order[rank] = i;
}

// ---- packed f32x2 helpers ----
__device__ __forceinline__ unsigned long long fma2(unsigned long long a,
                                                   unsigned long long b,
                                                   unsigned long long c) {
    unsigned long long d;
    asm("fma.rn.f32x2 %0, %1, %2, %3;" : "=l"(d) : "l"(a), "l"(b), "l"(c));
    return d;
}
__device__ __forceinline__ unsigned long long add2(unsigned long long a,
                                                   unsigned long long b) {
    unsigned long long d;
    asm("add.rn.f32x2 %0, %1, %2;" : "=l"(d) : "l"(a), "l"(b));
    return d;
}
__device__ __forceinline__ unsigned long long pack2(float x, float y) {
    unsigned long long r;
    asm("mov.b64 %0, {%1, %2};" : "=l"(r) : "f"(x), "f"(y));
    return r;
}
__device__ __forceinline__ void unpack2(unsigned long long v, float& x, float& y) {
    asm("mov.b64 {%0, %1}, %2;" : "=f"(x), "=f"(y) : "l"(v));
}

__device__ __forceinline__ float tanh_fast(float v) {
    float r;
    asm("tanh.approx.f32 %0, %1;" : "=f"(r) : "f"(v));
    return r;
}

// Roles: tid 0..127 -> z-rows (128+j); 128..255 -> n-rows (256+j);
// 256..383 -> r-rows (j) + combiner (highest warps = arbiter priority).
// Trio t = {warp t, warp t+4, warp t+8} syncs via named barrier 1+t (96 thr).
__global__ void __launch_bounds__(NTHREADS, 1)
gru_kernel(const float* __restrict__ x,        // [B, T, 2]
           const int*   __restrict__ lengths,  // [B]
           const float* __restrict__ W_ih,     // [384, 2]
           const float* __restrict__ W_hh,     // [384, 128]
           const float* __restrict__ b_ih,     // [384]
           const float* __restrict__ b_hh,     // [384]
           const float* __restrict__ head_w,   // [128]
           const float* __restrict__ head_b,   // [1]
           float*       __restrict__ out)      // [B, 1]
{
    __shared__ __align__(16) float sh_x[TT * 2];     // 16 KB
    __shared__ __align__(16) float sh_h[2][HH];      // ping-pong hidden state
    __shared__ __align__(8)  float sh_gzn[2 * HH];   // interleaved (gz, gn) per j
    __shared__ float sh_red[4];

    const int tid = threadIdx.x;
    const int b = d_order[blockIdx.x];
    const int len = lengths[b];

    const int role = tid >> 7;            // 0=z, 1=n, 2=r/combiner
    const int j = tid & 127;
    const int row = (role == 0) ? (HH + j) : (role == 1) ? (2 * HH + j) : j;
    const int bar_id = 1 + ((tid >> 5) & 3);

    // --- load input prefix into shared ---
    {
        const float4* xs = reinterpret_cast<const float4*>(x + (size_t)b * (TT * 2));
        float4* xd = reinterpret_cast<float4*>(sh_x);
        int nq = (len * 2 + 3) >> 2;
        for (int q = tid; q < nq; q += NTHREADS) xd[q] = xs[q];
    }

    // --- W_hh row into 64 packed f32x2 registers ---
    unsigned long long w[64];
    {
        const unsigned long long* wrow =
            reinterpret_cast<const unsigned long long*>(W_hh + (size_t)row * HH);
        #pragma unroll
        for (int t = 0; t < 64; t++) w[t] = wrow[t];
    }
    const float bhh = b_hh[row];

    // Combiner constants with sigma prescale folded in:
    //   sigma(v) = 0.5 + 0.5*tanh(0.5*v)  ->  store 0.5*W_ih and 0.5*b for r,z.
    float rw0 = 0.f, rw1 = 0.f, rb = 0.f;
    float zw0 = 0.f, zw1 = 0.f, zb = 0.f;
    float nw0 = 0.f, nw1 = 0.f, nb = 0.f, hw = 0.f;
    float h = 0.0f;
    if (role == 2) {
        float2 t2;
        t2 = *reinterpret_cast<const float2*>(W_ih + (size_t)j * 2);
        rw0 = 0.5f * t2.x; rw1 = 0.5f * t2.y;
        t2 = *reinterpret_cast<const float2*>(W_ih + (size_t)(HH + j) * 2);
        zw0 = 0.5f * t2.x; zw1 = 0.5f * t2.y;
        t2 = *reinterpret_cast<const float2*>(W_ih + (size_t)(2 * HH + j) * 2);
        nw0 = t2.x; nw1 = t2.y;
        rb = 0.5f * b_ih[j];
        zb = 0.5f * b_ih[HH + j];
        nb = b_ih[2 * HH + j];
        hw = head_w[j];
        sh_h[0][j] = 0.0f;
    }
    float* part_dst = sh_gzn + 2 * j + ((role == 1) ? 1 : 0);  // role 0 -> gz, 1 -> gn
    __syncthreads();

    int cur = 0;
    for (int t = 0; t < len; t++) {
        // x projections: combiner warps only (warp-uniform branch; saves
        // ~24 fma-pipe cyc/step of multiply-by-zero on the 8 z/n warps).
        float xr2 = 0.f, xz2 = 0.f, xn = 0.f;
        if (role == 2) {
            float2 xt = *reinterpret_cast<const float2*>(sh_x + 2 * t);
            xr2 = fmaf(rw0, xt.x, fmaf(rw1, xt.y, rb));   // 0.5*(Wr.x + br)
            xz2 = fmaf(zw0, xt.x, fmaf(zw1, xt.y, zb));   // 0.5*(Wz.x + bz)
            xn  = fmaf(nw0, xt.x, fmaf(nw1, xt.y, nb));
        }

        // gh = b_hh[row] + W_hh[row] . h   (4 FMA2 chains)
        unsigned long long acc0 = pack2(bhh, 0.0f);
        unsigned long long acc1 = pack2(0.0f, 0.0f);
        unsigned long long acc2 = acc1, acc3 = acc1;
        const ulonglong2* h2 = reinterpret_cast<const ulonglong2*>(sh_h[cur]);
        #pragma unroll
        for (int k = 0; k < 16; k++) {
            ulonglong2 ha = h2[2 * k];
            ulonglong2 hb = h2[2 * k + 1];
            acc0 = fma2(w[4 * k + 0], ha.x, acc0);
            acc1 = fma2(w[4 * k + 1], ha.y, acc1);
            acc2 = fma2(w[4 * k + 2], hb.x, acc2);
            acc3 = fma2(w[4 * k + 3], hb.y, acc3);
        }
        unsigned long long s = add2(add2(acc0, acc1), add2(acc2, acc3));
        float slo, shi;
        unpack2(s, slo, shi);
        float gh = slo + shi;

        if (role != 2) {
            *part_dst = gh;                               // gz or gn partial
            asm volatile("bar.arrive %0, 96;" :: "r"(bar_id) : "memory");
        } else {
            asm volatile("bar.sync %0, 96;" :: "r"(bar_id) : "memory");
            float2 gzn = *reinterpret_cast<const float2*>(sh_gzn + 2 * j);
            // r_t = tanh(0.5*(xr + gr));  r = 0.5 + 0.5*r_t (folded below)
            float r_t = tanh_fast(fmaf(0.5f, gh, xr2));
            float z_t = tanh_fast(fmaf(0.5f, gzn.x, xz2));
            // n = tanh(xn + r*gn) with r*gn = 0.5*gn + 0.5*r_t*gn
            float gn_half = 0.5f * gzn.y;
            float n = tanh_fast(fmaf(r_t, gn_half, xn + gn_half));
            // h' = (1-z)*n + z*h, z = 0.5+0.5*z_t  ->  0.5*((h+n) + z_t*(h-n))
            float hmn = h - n;
            float hpn = h + n;
            h = 0.5f * fmaf(z_t, hmn, hpn);
            sh_h[cur ^ 1][j] = h;
        }
        __syncthreads();
        cur ^= 1;
    }

    // --- head: out[b] = sum_j h[j]*head_w[j] + head_b ---
    if (role == 2) {
        float v = h * hw;
        #pragma unroll
        for (int o = 16; o > 0; o >>= 1) v += __shfl_down_sync(0xffffffffu, v, o);
        if ((tid & 31) == 0) sh_red[(tid >> 5) - 8] = v;
    }
    __syncthreads();
    if (tid == 256) {
        out[b] = (sh_red[0] + sh_red[1]) + (sh_red[2] + sh_red[3]) + head_b[0];
    }
}

extern "C" void kernel_launch(void* const* d_in, const int* in_sizes, int n_in,
                              void* d_out, int out_size) {
    const float* x      = (const float*)d_in[0];
    const int*   len    = (const int*)  d_in[1];
    const float* W_ih   = (const float*)d_in[2];
    const float* W_hh   = (const float*)d_in[3];
    const float* b_ih   = (const float*)d_in[4];
    const float* b_hh   = (const float*)d_in[5];
    const float* head_w = (const float*)d_in[6];
    const float* head_b = (const float*)d_in[7];
    float* out = (float*)d_out;

    order_kernel<<<1, BB>>>(len);
    gru_kernel<<<BB, NTHREADS>>>(x, len, W_ih, W_hh, b_ih, b_hh,
                                 head_w, head_b, out);
}

// round 6
// speedup vs baseline: 1.0536x; 1.0536x over previous
#include <cuda_runtime.h>

// Problem constants: B=256, T=2048, I=2, H=128, 3H=384
#define BB 256
#define TT 2048
#define HH 128
#define NTHREADS 384

__device__ int d_order[BB];

// Plain descending-length order (R2-proven best): wave 1 = 148 longest,
// wave-2 CTAs work-stolen in bid order = LPT.
__global__ void order_kernel(const int* __restrict__ lengths) {
    int i = threadIdx.x;
    int li = lengths[i];
    int rank = 0;
    #pragma unroll 8
    for (int j = 0; j < BB; j++) {
        int lj = lengths[j];
        rank += (lj > li) || (lj == li && j < i);
    }
    d_order[rank] = i;
}

// ---- packed f32x2 helpers ----
__device__ __forceinline__ unsigned long long fma2(unsigned long long a,
                                                   unsigned long long b,
                                                   unsigned long long c) {
    unsigned long long d;
    asm("fma.rn.f32x2 %0, %1, %2, %3;" : "=l"(d) : "l"(a), "l"(b), "l"(c));
    return d;
}
__device__ __forceinline__ unsigned long long add2(unsigned long long a,
                                                   unsigned long long b) {
    unsigned long long d;
    asm("add.rn.f32x2 %0, %1, %2;" : "=l"(d) : "l"(a), "l"(b));
    return d;
}
__device__ __forceinline__ unsigned long long pack2(float x, float y) {
    unsigned long long r;
    asm("mov.b64 %0, {%1, %2};" : "=l"(r) : "f"(x), "f"(y));
    return r;
}
__device__ __forceinline__ void unpack2(unsigned long long v, float& x, float& y) {
    asm("mov.b64 {%0, %1}, %2;" : "=f"(x), "=f"(y) : "l"(v));
}

__device__ __forceinline__ float tanh_fast(float v) {
    float r;
    asm("tanh.approx.f32 %0, %1;" : "=f"(r) : "f"(v));
    return r;
}

// Roles: tid 0..127 -> z-rows (128+j); 128..255 -> n-rows (256+j);
// 256..383 -> r-rows (j) + combiner (highest warps = arbiter priority).
// Trio t = {warp t, warp t+4, warp t+8} syncs via named barrier 1+t (96 thr).
// NOTE: hot loop is branch-free except the single warp-uniform role split at
// the barrier (unavoidable); x-projection runs on ALL warps with zero
// constants — R5 proved an if{} there costs BSSY/BSYNC > the saved FMAs.
__global__ void __launch_bounds__(NTHREADS, 1)
gru_kernel(const float* __restrict__ x,        // [B, T, 2]
           const int*   __restrict__ lengths,  // [B]
           const float* __restrict__ W_ih,     // [384, 2]
           const float* __restrict__ W_hh,     // [384, 128]
           const float* __restrict__ b_ih,     // [384]
           const float* __restrict__ b_hh,     // [384]
           const float* __restrict__ head_w,   // [128]
           const float* __restrict__ head_b,   // [1]
           float*       __restrict__ out)      // [B, 1]
{
    __shared__ __align__(16) float sh_x[TT * 2];     // 16 KB
    __shared__ __align__(16) float sh_h[2][HH];      // ping-pong hidden state
    __shared__ __align__(8)  float sh_gzn[2 * HH];   // interleaved (gz, gn) per j
    __shared__ float sh_red[4];

    const int tid = threadIdx.x;
    const int b = d_order[blockIdx.x];
    const int len = lengths[b];

    const int role = tid >> 7;            // 0=z, 1=n, 2=r/combiner
    const int j = tid & 127;
    const int row = (role == 0) ? (HH + j) : (role == 1) ? (2 * HH + j) : j;
    const int bar_id = 1 + ((tid >> 5) & 3);

    // --- load input prefix into shared ---
    {
        const float4* xs = reinterpret_cast<const float4*>(x + (size_t)b * (TT * 2));
        float4* xd = reinterpret_cast<float4*>(sh_x);
        int nq = (len * 2 + 3) >> 2;
        for (int q = tid; q < nq; q += NTHREADS) xd[q] = xs[q];
    }

    // --- W_hh row into 64 packed f32x2 registers ---
    unsigned long long w[64];
    {
        const unsigned long long* wrow =
            reinterpret_cast<const unsigned long long*>(W_hh + (size_t)row * HH);
        #pragma unroll
        for (int t = 0; t < 64; t++) w[t] = wrow[t];
    }
    const float bhh = b_hh[row];

    // Combiner constants with sigma prescale folded in:
    //   sigma(v) = 0.5 + 0.5*tanh(0.5*v)  ->  store 0.5*W_ih, 0.5*b for r,z.
    // Zeros on non-combiner threads (branch-free x-projection).
    float rw0 = 0.f, rw1 = 0.f, rb = 0.f;
    float zw0 = 0.f, zw1 = 0.f, zb = 0.f;
    float nw0 = 0.f, nw1 = 0.f, nb = 0.f, hw = 0.f;
    float h = 0.0f;
    if (role == 2) {
        float2 t2;
        t2 = *reinterpret_cast<const float2*>(W_ih + (size_t)j * 2);
        rw0 = 0.5f * t2.x; rw1 = 0.5f * t2.y;
        t2 = *reinterpret_cast<const float2*>(W_ih + (size_t)(HH + j) * 2);
        zw0 = 0.5f * t2.x; zw1 = 0.5f * t2.y;
        t2 = *reinterpret_cast<const float2*>(W_ih + (size_t)(2 * HH + j) * 2);
        nw0 = t2.x; nw1 = t2.y;
        rb = 0.5f * b_ih[j];
        zb = 0.5f * b_ih[HH + j];
        nb = b_ih[2 * HH + j];
        hw = head_w[j];
        sh_h[0][j] = 0.0f;
    }
    float* part_dst = sh_gzn + 2 * j + ((role == 1) ? 1 : 0);  // 0 -> gz, 1 -> gn
    __syncthreads();

    int cur = 0;
    for (int t = 0; t < len; t++) {
        // x projections (all warps, zero constants on z/n; h-independent,
        // hoisted off the serial tail).
        float2 xt = *reinterpret_cast<const float2*>(sh_x + 2 * t);
        float xr2 = fmaf(rw0, xt.x, fmaf(rw1, xt.y, rb));   // 0.5*(Wr.x + br)
        float xz2 = fmaf(zw0, xt.x, fmaf(zw1, xt.y, zb));   // 0.5*(Wz.x + bz)
        float xn  = fmaf(nw0, xt.x, fmaf(nw1, xt.y, nb));

        // gh = b_hh[row] + W_hh[row] . h   (4 FMA2 chains)
        unsigned long long acc0 = pack2(bhh, 0.0f);
        unsigned long long acc1 = pack2(0.0f, 0.0f);
        unsigned long long acc2 = acc1, acc3 = acc1;
        const ulonglong2* h2 = reinterpret_cast<const ulonglong2*>(sh_h[cur]);
        #pragma unroll
        for (int k = 0; k < 16; k++) {
            ulonglong2 ha = h2[2 * k];
            ulonglong2 hb = h2[2 * k + 1];
            acc0 = fma2(w[4 * k + 0], ha.x, acc0);
            acc1 = fma2(w[4 * k + 1], ha.y, acc1);
            acc2 = fma2(w[4 * k + 2], hb.x, acc2);
            acc3 = fma2(w[4 * k + 3], hb.y, acc3);
        }
        unsigned long long s = add2(add2(acc0, acc1), add2(acc2, acc3));
        float slo, shi;
        unpack2(s, slo, shi);
        float gh = slo + shi;

        if (role != 2) {
            *part_dst = gh;                               // gz or gn partial
            asm volatile("bar.arrive %0, 96;" :: "r"(bar_id) : "memory");
        } else {
            asm volatile("bar.sync %0, 96;" :: "r"(bar_id) : "memory");
            float2 gzn = *reinterpret_cast<const float2*>(sh_gzn + 2 * j);
            float r_t = tanh_fast(fmaf(0.5f, gh, xr2));     // tanh(0.5*(xr+gr))
            float z_t = tanh_fast(fmaf(0.5f, gzn.x, xz2));
            float gn_half = 0.5f * gzn.y;
            float n = tanh_fast(fmaf(r_t, gn_half, xn + gn_half)); // xn + r*gn
            float hmn = h - n;
            float hpn = h + n;
            h = 0.5f * fmaf(z_t, hmn, hpn);   // (1-z)*n + z*h, z=0.5+0.5*z_t
            sh_h[cur ^ 1][j] = h;
        }
        __syncthreads();
        cur ^= 1;
    }

    // --- head: out[b] = sum_j h[j]*head_w[j] + head_b ---
    if (role == 2) {
        float v = h * hw;
        #pragma unroll
        for (int o = 16; o > 0; o >>= 1) v += __shfl_down_sync(0xffffffffu, v, o);
        if ((tid & 31) == 0) sh_red[(tid >> 5) - 8] = v;
    }
    __syncthreads();
    if (tid == 256) {
        out[b] = (sh_red[0] + sh_red[1]) + (sh_red[2] + sh_red[3]) + head_b[0];
    }
}

extern "C" void kernel_launch(void* const* d_in, const int* in_sizes, int n_in,
                              void* d_out, int out_size) {
    const float* x      = (const float*)d_in[0];
    const int*   len    = (const int*)  d_in[1];
    const float* W_ih   = (const float*)d_in[2];
    const float* W_hh   = (const float*)d_in[3];
    const float* b_ih   = (const float*)d_in[4];
    const float* b_hh   = (const float*)d_in[5];
    const float* head_w = (const float*)d_in[6];
    const float* head_b = (const float*)d_in[7];
    float* out = (float*)d_out;

    order_kernel<<<1, BB>>>(len);
    gru_kernel<<<BB, NTHREADS>>>(x, len, W_ih, W_hh, b_ih, b_hh,
                                 head_w, head_b, out);
}